// round 1
// baseline (speedup 1.0000x reference)
#include <cuda_runtime.h>
#include <cuda_fp16.h>
#include <stdint.h>

// Problem dims (fixed by setup_inputs)
#define NB   32
#define NT   512
#define DIN  512
#define HID  1024
#define NLAYERS 4
#define NOUT 1024

#define NCTA     128     // 32 gate-cols each (8 h-dims x 4 gates)
#define NTHREADS 256     // 8 warps
#define ASTRIDE  1032    // halfs per A row (1024 + 8 pad -> conflict-free LDS)
#define WSTRIDE  2056    // halfs per W row (2048 + 8 pad)

// ---------- scratch (static device globals; no allocation allowed) ----------
__device__ __half  g_xT[(size_t)NT*NB*DIN];    // x transposed to time-major, fp16
__device__ __half  g_hsA[(size_t)NT*NB*HID];   // hs ping
__device__ __half  g_hsB[(size_t)NT*NB*HID];   // hs pong
__device__ float   g_hlast[NB*HID];            // final-layer h at t = T-1 (fp32)
__device__ unsigned g_bar;                     // grid barrier counter

// ---------- helpers ----------
__global__ void reset_kernel() { if (threadIdx.x == 0) g_bar = 0u; }

// x[B][T][DIN] fp32 -> g_xT[T][B][DIN] fp16
__global__ void xT_kernel(const float* __restrict__ x) {
    size_t n = (size_t)NT * NB * DIN;
    for (size_t idx = (size_t)blockIdx.x * blockDim.x + threadIdx.x; idx < n;
         idx += (size_t)gridDim.x * blockDim.x) {
        int d = (int)(idx % DIN);
        size_t r = idx / DIN;
        int b = (int)(r % NB);
        int t = (int)(r / NB);
        g_xT[idx] = __float2half(x[((size_t)b * NT + t) * DIN + d]);
    }
}

__device__ __forceinline__ void bar_wait(unsigned nbar) {
    if (threadIdx.x == 0) {
        unsigned target = nbar * NCTA;
        while (*(volatile unsigned*)&g_bar < target) { }
        __threadfence();   // acquire
    }
    __syncthreads();
}

__device__ __forceinline__ void bar_arrive() {
    __syncthreads();                    // all h-stores of this CTA done
    if (threadIdx.x == 0) {
        __threadfence();                // release (cumulative over CTA via bar.sync)
        atomicAdd(&g_bar, 1u);
    }
}

// One K-chunk of the per-step GEMM: acc += A[32,chunkK] * W[:, wkbase:wkbase+chunkK]^T
// 8 warps partition chunkK; each warp covers all 32 local cols, M=32 (2 m16 tiles).
__device__ __forceinline__ void mma_chunk(float acc[2][4][4],
                                          const __half* __restrict__ Asm,
                                          const __half* __restrict__ Wsm,
                                          int wkbase, int chunkK,
                                          int wid, int g, int tig) {
    const int Kw  = chunkK >> 3;   // per-warp K
    const int kk0 = wid * Kw;
    #pragma unroll 2
    for (int kt = 0; kt < Kw; kt += 16) {
        const int kk = kk0 + kt;
        uint32_t a[2][4];
        #pragma unroll
        for (int mt = 0; mt < 2; ++mt) {
            const __half* ap = Asm + (mt * 16 + g) * ASTRIDE + kk + 2 * tig;
            a[mt][0] = *(const uint32_t*)(ap);
            a[mt][1] = *(const uint32_t*)(ap + 8 * ASTRIDE);
            a[mt][2] = *(const uint32_t*)(ap + 8);
            a[mt][3] = *(const uint32_t*)(ap + 8 * ASTRIDE + 8);
        }
        #pragma unroll
        for (int nt = 0; nt < 4; ++nt) {
            const __half* bp = Wsm + (nt * 8 + g) * WSTRIDE + wkbase + kk + 2 * tig;
            uint32_t b0 = *(const uint32_t*)(bp);
            uint32_t b1 = *(const uint32_t*)(bp + 8);
            #pragma unroll
            for (int mt = 0; mt < 2; ++mt) {
                asm volatile(
                    "mma.sync.aligned.m16n8k16.row.col.f32.f16.f16.f32 "
                    "{%0,%1,%2,%3},{%4,%5,%6,%7},{%8,%9},{%0,%1,%2,%3};\n"
                    : "+f"(acc[mt][nt][0]), "+f"(acc[mt][nt][1]),
                      "+f"(acc[mt][nt][2]), "+f"(acc[mt][nt][3])
                    : "r"(a[mt][0]), "r"(a[mt][1]), "r"(a[mt][2]), "r"(a[mt][3]),
                      "r"(b0), "r"(b1));
            }
        }
    }
}

// ---------- persistent LSTM kernel ----------
extern __shared__ __half s_mem[];

__global__ __launch_bounds__(NTHREADS, 1)
void lstm_kernel(const float* __restrict__ h0, const float* __restrict__ c0,
                 const float* __restrict__ W0, const float* __restrict__ b0,
                 const float* __restrict__ Wl, const float* __restrict__ bl) {
    __half* Wsm = s_mem;                              // [32][WSTRIDE] fp16
    __half* Asm = s_mem + 32 * WSTRIDE;               // [32][ASTRIDE] fp16 (one chunk)
    float*  bias = (float*)(s_mem + 32 * WSTRIDE + 32 * ASTRIDE);  // 32 floats
    float*  partials = (float*)Asm;                   // reuse A region: 8*1024 f32
    float*  zbuf     = partials + 8 * 1024;           // +1024 f32

    const int cta  = blockIdx.x;
    const int tid  = threadIdx.x;
    const int wid  = tid >> 5;
    const int lane = tid & 31;
    const int g    = lane >> 2;       // mma groupID
    const int tig  = lane & 3;        // mma threadID-in-group
    const int rb   = tid >> 3;        // batch owned for gate math (0..31)
    const int rd   = tid & 7;         // local h-dim owned (0..7)
    const int dimg = cta * 8 + rd;    // global h-dim owned

    float c_state = 0.f;

    for (int l = 0; l < NLAYERS; ++l) {
        const float* W  = (l == 0) ? W0 : (Wl + (size_t)(l - 1) * 2048 * 4096);
        const float* bv = (l == 0) ? b0 : (bl + (size_t)(l - 1) * 4096);
        const int Kin  = (l == 0) ? DIN : HID;
        const int Ktot = Kin + HID;

        // Load this CTA's weight slice, transposed to [col][k], fp16.
        for (int idx = tid; idx < 32 * Ktot; idx += NTHREADS) {
            int c = idx & 31;
            int k = idx >> 5;
            int colG = (c >> 3) * HID + cta * 8 + (c & 7);
            Wsm[c * WSTRIDE + k] = __float2half(W[(size_t)k * 4096 + colG]);
        }
        if (tid < 32) bias[tid] = bv[(tid >> 3) * HID + cta * 8 + (tid & 7)];
        c_state = c0[(size_t)l * NB * HID + (size_t)rb * HID + dimg];
        __syncthreads();

        const __half* hs_prev = (l & 1) ? g_hsB : g_hsA;   // layer 0 uses g_xT instead
        __half*       hs_cur  = (l & 1) ? g_hsA : g_hsB;

        if (l > 0) bar_wait((unsigned)l * NT);   // previous layer fully written

        for (int t = 0; t < NT; ++t) {
            float acc[2][4][4];
            #pragma unroll
            for (int i = 0; i < 2; ++i)
                #pragma unroll
                for (int j = 0; j < 4; ++j)
                    #pragma unroll
                    for (int k2 = 0; k2 < 4; ++k2) acc[i][j][k2] = 0.f;

            // ---- stage chunk0: input part (x_t or hs_prev[t]) — no h dependency ----
            {
                const __half* src = (l == 0) ? (g_xT + (size_t)t * NB * DIN)
                                             : (hs_prev + (size_t)t * NB * HID);
                const int kin8 = Kin >> 3;
                for (int i = tid; i < NB * kin8; i += NTHREADS) {
                    int b  = i / kin8;
                    int kk = (i - b * kin8) << 3;
                    uint4 v = __ldcg((const uint4*)(src + (size_t)b * Kin + kk));
                    *(uint4*)(Asm + b * ASTRIDE + kk) = v;
                }
            }
            __syncthreads();
            mma_chunk(acc, Asm, Wsm, 0, Kin, wid, g, tig);

            // ---- wait for h(t-1) from all CTAs (overlapped barrier: arrived early) ----
            if (t > 0) bar_wait((unsigned)l * NT + (unsigned)t);
            else       __syncthreads();    // protect Asm overwrite after chunk0 mma

            // ---- stage chunk1: recurrent h part ----
            if (t == 0) {
                const float* hsrc = h0 + (size_t)l * NB * HID;
                for (int i = tid; i < NB * (HID / 4); i += NTHREADS) {
                    int b  = i >> 8;            // HID/4 = 256
                    int kk = (i & 255) << 2;
                    float4 v = *(const float4*)(hsrc + (size_t)b * HID + kk);
                    __half2* dst = (__half2*)(Asm + b * ASTRIDE + kk);
                    dst[0] = __floats2half2_rn(v.x, v.y);
                    dst[1] = __floats2half2_rn(v.z, v.w);
                }
            } else {
                const __half* hsrc = hs_cur + (size_t)(t - 1) * NB * HID;
                for (int i = tid; i < NB * (HID / 8); i += NTHREADS) {
                    int b  = i >> 7;            // HID/8 = 128
                    int kk = (i & 127) << 3;
                    uint4 v = __ldcg((const uint4*)(hsrc + (size_t)b * HID + kk));
                    *(uint4*)(Asm + b * ASTRIDE + kk) = v;
                }
            }
            __syncthreads();
            mma_chunk(acc, Asm, Wsm, Kin, HID, wid, g, tig);
            __syncthreads();   // A reads done; reuse region for partials

            // ---- cross-warp reduction: store partial [32x32] per warp ----
            {
                float* P = partials + wid * 1024;
                #pragma unroll
                for (int mt = 0; mt < 2; ++mt) {
                    #pragma unroll
                    for (int nt = 0; nt < 4; ++nt) {
                        int r = mt * 16 + g, cc = nt * 8 + 2 * tig;
                        *(float2*)(P + r * 32 + cc) =
                            make_float2(acc[mt][nt][0], acc[mt][nt][1]);
                        *(float2*)(P + (r + 8) * 32 + cc) =
                            make_float2(acc[mt][nt][2], acc[mt][nt][3]);
                    }
                }
            }
            __syncthreads();

            // tree-free reduce: each thread sums 4 contiguous elems over 8 warps
            {
                int e0 = tid * 4;
                float4 s = make_float4(0.f, 0.f, 0.f, 0.f);
                #pragma unroll
                for (int w = 0; w < 8; ++w) {
                    float4 v = *(const float4*)(partials + w * 1024 + e0);
                    s.x += v.x; s.y += v.y; s.z += v.z; s.w += v.w;
                }
                *(float4*)(zbuf + e0) = s;
            }
            __syncthreads();

            // ---- gates + state update (thread owns one (b, dim) pair) ----
            {
                float zi = zbuf[rb * 32 +  0 + rd] + bias[ 0 + rd];
                float zf = zbuf[rb * 32 +  8 + rd] + bias[ 8 + rd];
                float zg = zbuf[rb * 32 + 16 + rd] + bias[16 + rd];
                float zo = zbuf[rb * 32 + 24 + rd] + bias[24 + rd];
                float si = 1.f / (1.f + __expf(-zi));
                float sf = 1.f / (1.f + __expf(-zf));
                float so = 1.f / (1.f + __expf(-zo));
                float tg = tanhf(zg);
                c_state = sf * c_state + si * tg;
                float h = so * tanhf(c_state);
                hs_cur[(size_t)t * NB * HID + (size_t)rb * HID + dimg] = __float2half(h);
                if (l == NLAYERS - 1 && t == NT - 1)
                    g_hlast[rb * HID + dimg] = h;
            }
            bar_arrive();
        }
    }
}

// ---------- dense head: out = h_last @ Wout + bout ----------
__global__ void head_kernel(const float* __restrict__ Wout,
                            const float* __restrict__ bout,
                            float* __restrict__ out) {
    __shared__ float hsh[HID];
    int b = blockIdx.x;
    for (int i = threadIdx.x; i < HID; i += blockDim.x) hsh[i] = g_hlast[b * HID + i];
    __syncthreads();
    for (int o = threadIdx.x; o < NOUT; o += blockDim.x) {
        float s = bout[o];
        #pragma unroll 8
        for (int k = 0; k < HID; ++k) s += hsh[k] * Wout[(size_t)k * NOUT + o];
        out[(size_t)b * NOUT + o] = s;
    }
}

// ---------- launch ----------
extern "C" void kernel_launch(void* const* d_in, const int* in_sizes, int n_in,
                              void* d_out, int out_size) {
    const float* x    = (const float*)d_in[0];
    const float* h0   = (const float*)d_in[1];
    const float* c0   = (const float*)d_in[2];
    const float* W0   = (const float*)d_in[3];
    const float* b0   = (const float*)d_in[4];
    const float* Wl   = (const float*)d_in[5];
    const float* bl   = (const float*)d_in[6];
    const float* Wout = (const float*)d_in[7];
    const float* bout = (const float*)d_in[8];
    float* out = (float*)d_out;

    size_t smem = (size_t)(32 * WSTRIDE + 32 * ASTRIDE) * sizeof(__half)
                + 32 * sizeof(float);   // 197,760 B
    cudaFuncSetAttribute(lstm_kernel,
                         cudaFuncAttributeMaxDynamicSharedMemorySize, (int)smem);

    reset_kernel<<<1, 32>>>();                       // deterministic barrier state
    xT_kernel<<<1024, 256>>>(x);                     // x -> time-major fp16
    lstm_kernel<<<NCTA, NTHREADS, smem>>>(h0, c0, W0, b0, Wl, bl);
    head_kernel<<<NB, 1024>>>(Wout, bout, out);
}

// round 2
// speedup vs baseline: 1.0010x; 1.0010x over previous
#include <cuda_runtime.h>
#include <cuda_fp16.h>
#include <stdint.h>

// Problem dims (fixed by setup_inputs)
#define NB   32
#define NT   512
#define DIN  512
#define HID  1024
#define NLAYERS 4
#define NOUT 1024

#define NCTA     128     // 32 gate-cols each (8 h-dims x 4 gates)
#define NTHREADS 256     // 8 warps
#define ASTRIDE  1032    // halfs per A row (1024 + 8 pad -> conflict-free LDS)
#define WSTRIDE  2056    // halfs per W row (2048 + 8 pad)

// ---------- scratch (static device globals; no allocation allowed) ----------
__device__ __half  g_xT[(size_t)NT*NB*DIN];    // x transposed to time-major, fp16
__device__ __half  g_hsA[(size_t)NT*NB*HID];   // hs ping
__device__ __half  g_hsB[(size_t)NT*NB*HID];   // hs pong
__device__ float   g_hlast[NB*HID];            // final-layer h at t = T-1 (fp32)
__device__ unsigned g_bar;                     // grid barrier counter

// ---------- helpers ----------
__global__ void reset_kernel() { if (threadIdx.x == 0) g_bar = 0u; }

// x[B][T][DIN] fp32 -> g_xT[T][B][DIN] fp16
__global__ void xT_kernel(const float* __restrict__ x) {
    size_t n = (size_t)NT * NB * DIN;
    for (size_t idx = (size_t)blockIdx.x * blockDim.x + threadIdx.x; idx < n;
         idx += (size_t)gridDim.x * blockDim.x) {
        int d = (int)(idx % DIN);
        size_t r = idx / DIN;
        int b = (int)(r % NB);
        int t = (int)(r / NB);
        g_xT[idx] = __float2half(x[((size_t)b * NT + t) * DIN + d]);
    }
}

__device__ __forceinline__ void bar_wait(unsigned nbar) {
    if (threadIdx.x == 0) {
        unsigned target = nbar * NCTA;
        while (*(volatile unsigned*)&g_bar < target) { }
        __threadfence();   // acquire
    }
    __syncthreads();
}

__device__ __forceinline__ void bar_arrive() {
    __syncthreads();                    // all h-stores of this CTA done
    if (threadIdx.x == 0) {
        __threadfence();                // release (cumulative over CTA via bar.sync)
        atomicAdd(&g_bar, 1u);
    }
}

// One K-chunk of the per-step GEMM: acc += A[32,chunkK] * W[:, wkbase:wkbase+chunkK]^T
// 8 warps partition chunkK; each warp covers all 32 local cols, M=32 (2 m16 tiles).
__device__ __forceinline__ void mma_chunk(float acc[2][4][4],
                                          const __half* __restrict__ Asm,
                                          const __half* __restrict__ Wsm,
                                          int wkbase, int chunkK,
                                          int wid, int g, int tig) {
    const int Kw  = chunkK >> 3;   // per-warp K
    const int kk0 = wid * Kw;
    #pragma unroll 2
    for (int kt = 0; kt < Kw; kt += 16) {
        const int kk = kk0 + kt;
        uint32_t a[2][4];
        #pragma unroll
        for (int mt = 0; mt < 2; ++mt) {
            const __half* ap = Asm + (mt * 16 + g) * ASTRIDE + kk + 2 * tig;
            a[mt][0] = *(const uint32_t*)(ap);
            a[mt][1] = *(const uint32_t*)(ap + 8 * ASTRIDE);
            a[mt][2] = *(const uint32_t*)(ap + 8);
            a[mt][3] = *(const uint32_t*)(ap + 8 * ASTRIDE + 8);
        }
        #pragma unroll
        for (int nt = 0; nt < 4; ++nt) {
            const __half* bp = Wsm + (nt * 8 + g) * WSTRIDE + wkbase + kk + 2 * tig;
            uint32_t b0 = *(const uint32_t*)(bp);
            uint32_t b1 = *(const uint32_t*)(bp + 8);
            #pragma unroll
            for (int mt = 0; mt < 2; ++mt) {
                asm volatile(
                    "mma.sync.aligned.m16n8k16.row.col.f32.f16.f16.f32 "
                    "{%0,%1,%2,%3},{%4,%5,%6,%7},{%8,%9},{%0,%1,%2,%3};\n"
                    : "+f"(acc[mt][nt][0]), "+f"(acc[mt][nt][1]),
                      "+f"(acc[mt][nt][2]), "+f"(acc[mt][nt][3])
                    : "r"(a[mt][0]), "r"(a[mt][1]), "r"(a[mt][2]), "r"(a[mt][3]),
                      "r"(b0), "r"(b1));
            }
        }
    }
}

// ---------- persistent LSTM kernel ----------
extern __shared__ __half s_mem[];

__global__ __launch_bounds__(NTHREADS, 1)
void lstm_kernel(const float* __restrict__ h0, const float* __restrict__ c0,
                 const float* __restrict__ W0, const float* __restrict__ b0,
                 const float* __restrict__ Wl, const float* __restrict__ bl) {
    __half* Wsm = s_mem;                              // [32][WSTRIDE] fp16
    __half* Asm = s_mem + 32 * WSTRIDE;               // [32][ASTRIDE] fp16 (one chunk)
    float*  bias = (float*)(s_mem + 32 * WSTRIDE + 32 * ASTRIDE);  // 32 floats
    float*  partials = (float*)Asm;                   // reuse A region: 8*1024 f32
    float*  zbuf     = partials + 8 * 1024;           // +1024 f32

    const int cta  = blockIdx.x;
    const int tid  = threadIdx.x;
    const int wid  = tid >> 5;
    const int lane = tid & 31;
    const int g    = lane >> 2;       // mma groupID
    const int tig  = lane & 3;        // mma threadID-in-group
    const int rb   = tid >> 3;        // batch owned for gate math (0..31)
    const int rd   = tid & 7;         // local h-dim owned (0..7)
    const int dimg = cta * 8 + rd;    // global h-dim owned

    float c_state = 0.f;

    for (int l = 0; l < NLAYERS; ++l) {
        const float* W  = (l == 0) ? W0 : (Wl + (size_t)(l - 1) * 2048 * 4096);
        const float* bv = (l == 0) ? b0 : (bl + (size_t)(l - 1) * 4096);
        const int Kin  = (l == 0) ? DIN : HID;
        const int Ktot = Kin + HID;

        // Load this CTA's weight slice, transposed to [col][k], fp16.
        for (int idx = tid; idx < 32 * Ktot; idx += NTHREADS) {
            int c = idx & 31;
            int k = idx >> 5;
            int colG = (c >> 3) * HID + cta * 8 + (c & 7);
            Wsm[c * WSTRIDE + k] = __float2half(W[(size_t)k * 4096 + colG]);
        }
        if (tid < 32) bias[tid] = bv[(tid >> 3) * HID + cta * 8 + (tid & 7)];
        c_state = c0[(size_t)l * NB * HID + (size_t)rb * HID + dimg];
        __syncthreads();

        const __half* hs_prev = (l & 1) ? g_hsB : g_hsA;   // layer 0 uses g_xT instead
        __half*       hs_cur  = (l & 1) ? g_hsA : g_hsB;

        if (l > 0) bar_wait((unsigned)l * NT);   // previous layer fully written

        for (int t = 0; t < NT; ++t) {
            float acc[2][4][4];
            #pragma unroll
            for (int i = 0; i < 2; ++i)
                #pragma unroll
                for (int j = 0; j < 4; ++j)
                    #pragma unroll
                    for (int k2 = 0; k2 < 4; ++k2) acc[i][j][k2] = 0.f;

            // ---- stage chunk0: input part (x_t or hs_prev[t]) — no h dependency ----
            {
                const __half* src = (l == 0) ? (g_xT + (size_t)t * NB * DIN)
                                             : (hs_prev + (size_t)t * NB * HID);
                const int kin8 = Kin >> 3;
                for (int i = tid; i < NB * kin8; i += NTHREADS) {
                    int b  = i / kin8;
                    int kk = (i - b * kin8) << 3;
                    uint4 v = __ldcg((const uint4*)(src + (size_t)b * Kin + kk));
                    *(uint4*)(Asm + b * ASTRIDE + kk) = v;
                }
            }
            __syncthreads();
            mma_chunk(acc, Asm, Wsm, 0, Kin, wid, g, tig);

            // ---- wait for h(t-1) from all CTAs (overlapped barrier: arrived early) ----
            if (t > 0) bar_wait((unsigned)l * NT + (unsigned)t);
            else       __syncthreads();    // protect Asm overwrite after chunk0 mma

            // ---- stage chunk1: recurrent h part ----
            if (t == 0) {
                const float* hsrc = h0 + (size_t)l * NB * HID;
                for (int i = tid; i < NB * (HID / 4); i += NTHREADS) {
                    int b  = i >> 8;            // HID/4 = 256
                    int kk = (i & 255) << 2;
                    float4 v = *(const float4*)(hsrc + (size_t)b * HID + kk);
                    __half2* dst = (__half2*)(Asm + b * ASTRIDE + kk);
                    dst[0] = __floats2half2_rn(v.x, v.y);
                    dst[1] = __floats2half2_rn(v.z, v.w);
                }
            } else {
                const __half* hsrc = hs_cur + (size_t)(t - 1) * NB * HID;
                for (int i = tid; i < NB * (HID / 8); i += NTHREADS) {
                    int b  = i >> 7;            // HID/8 = 128
                    int kk = (i & 127) << 3;
                    uint4 v = __ldcg((const uint4*)(hsrc + (size_t)b * HID + kk));
                    *(uint4*)(Asm + b * ASTRIDE + kk) = v;
                }
            }
            __syncthreads();
            mma_chunk(acc, Asm, Wsm, Kin, HID, wid, g, tig);
            __syncthreads();   // A reads done; reuse region for partials

            // ---- cross-warp reduction: store partial [32x32] per warp ----
            {
                float* P = partials + wid * 1024;
                #pragma unroll
                for (int mt = 0; mt < 2; ++mt) {
                    #pragma unroll
                    for (int nt = 0; nt < 4; ++nt) {
                        int r = mt * 16 + g, cc = nt * 8 + 2 * tig;
                        *(float2*)(P + r * 32 + cc) =
                            make_float2(acc[mt][nt][0], acc[mt][nt][1]);
                        *(float2*)(P + (r + 8) * 32 + cc) =
                            make_float2(acc[mt][nt][2], acc[mt][nt][3]);
                    }
                }
            }
            __syncthreads();

            // tree-free reduce: each thread sums 4 contiguous elems over 8 warps
            {
                int e0 = tid * 4;
                float4 s = make_float4(0.f, 0.f, 0.f, 0.f);
                #pragma unroll
                for (int w = 0; w < 8; ++w) {
                    float4 v = *(const float4*)(partials + w * 1024 + e0);
                    s.x += v.x; s.y += v.y; s.z += v.z; s.w += v.w;
                }
                *(float4*)(zbuf + e0) = s;
            }
            __syncthreads();

            // ---- gates + state update (thread owns one (b, dim) pair) ----
            {
                float zi = zbuf[rb * 32 +  0 + rd] + bias[ 0 + rd];
                float zf = zbuf[rb * 32 +  8 + rd] + bias[ 8 + rd];
                float zg = zbuf[rb * 32 + 16 + rd] + bias[16 + rd];
                float zo = zbuf[rb * 32 + 24 + rd] + bias[24 + rd];
                float si = 1.f / (1.f + __expf(-zi));
                float sf = 1.f / (1.f + __expf(-zf));
                float so = 1.f / (1.f + __expf(-zo));
                float tg = tanhf(zg);
                c_state = sf * c_state + si * tg;
                float h = so * tanhf(c_state);
                hs_cur[(size_t)t * NB * HID + (size_t)rb * HID + dimg] = __float2half(h);
                if (l == NLAYERS - 1 && t == NT - 1)
                    g_hlast[rb * HID + dimg] = h;
            }
            bar_arrive();
        }
    }
}

// ---------- dense head: out = h_last @ Wout + bout ----------
__global__ void head_kernel(const float* __restrict__ Wout,
                            const float* __restrict__ bout,
                            float* __restrict__ out) {
    __shared__ float hsh[HID];
    int b = blockIdx.x;
    for (int i = threadIdx.x; i < HID; i += blockDim.x) hsh[i] = g_hlast[b * HID + i];
    __syncthreads();
    for (int o = threadIdx.x; o < NOUT; o += blockDim.x) {
        float s = bout[o];
        #pragma unroll 8
        for (int k = 0; k < HID; ++k) s += hsh[k] * Wout[(size_t)k * NOUT + o];
        out[(size_t)b * NOUT + o] = s;
    }
}

// ---------- launch ----------
extern "C" void kernel_launch(void* const* d_in, const int* in_sizes, int n_in,
                              void* d_out, int out_size) {
    const float* x    = (const float*)d_in[0];
    const float* h0   = (const float*)d_in[1];
    const float* c0   = (const float*)d_in[2];
    const float* W0   = (const float*)d_in[3];
    const float* b0   = (const float*)d_in[4];
    const float* Wl   = (const float*)d_in[5];
    const float* bl   = (const float*)d_in[6];
    const float* Wout = (const float*)d_in[7];
    const float* bout = (const float*)d_in[8];
    float* out = (float*)d_out;

    size_t smem = (size_t)(32 * WSTRIDE + 32 * ASTRIDE) * sizeof(__half)
                + 32 * sizeof(float);   // 197,760 B
    cudaFuncSetAttribute(lstm_kernel,
                         cudaFuncAttributeMaxDynamicSharedMemorySize, (int)smem);

    reset_kernel<<<1, 32>>>();                       // deterministic barrier state
    xT_kernel<<<1024, 256>>>(x);                     // x -> time-major fp16
    lstm_kernel<<<NCTA, NTHREADS, smem>>>(h0, c0, W0, b0, Wl, bl);
    head_kernel<<<NB, 1024>>>(Wout, bout, out);
}

// round 3
// speedup vs baseline: 1.6651x; 1.6635x over previous
#include <cuda_runtime.h>
#include <cuda_fp16.h>
#include <stdint.h>

#define NB   32
#define NT   512
#define DIN  512
#define HID  1024
#define NOUT 1024
#define NCTA     128
#define NTHREADS 256

// ---------------- static device scratch ----------------
__device__ __half  g_xoct[(size_t)NT * 64 * NB * 8];          // x, octet layout
__device__ __half  g_ringA[(size_t)(NT + 1) * 128 * NB * 8];  // h ring (513 slots)
__device__ __half  g_ringB[(size_t)(NT + 1) * 128 * NB * 8];
__device__ __half  g_WT[(size_t)4096 * (1536 + 3 * 2048)];    // W^T fp16 [n][Ktot]
__device__ float   g_Z0[(size_t)NT * NB * 4096];              // precomputed input part
__device__ float   g_hlast[NB * HID];
__device__ unsigned g_bar;

__global__ void reset_kernel() { if (threadIdx.x == 0) g_bar = 0u; }

__device__ __forceinline__ void bar_wait(unsigned target) {
    if (threadIdx.x == 0) {
        while (*(volatile unsigned*)&g_bar < target) { }
        __threadfence();
    }
    __syncthreads();
}
__device__ __forceinline__ void bar_arrive() {
    __syncthreads();
    if (threadIdx.x == 0) { __threadfence(); atomicAdd(&g_bar, 1u); }
}

__device__ __forceinline__ void mma16816(float* c, const uint32_t* a, const uint32_t* b) {
    asm volatile(
        "mma.sync.aligned.m16n8k16.row.col.f32.f16.f16.f32 "
        "{%0,%1,%2,%3},{%4,%5,%6,%7},{%8,%9},{%0,%1,%2,%3};\n"
        : "+f"(c[0]), "+f"(c[1]), "+f"(c[2]), "+f"(c[3])
        : "r"(a[0]), "r"(a[1]), "r"(a[2]), "r"(a[3]), "r"(b[0]), "r"(b[1]));
}
__device__ __forceinline__ void cp16(void* s, const void* g) {
    uint32_t a = (uint32_t)__cvta_generic_to_shared(s);
    asm volatile("cp.async.cg.shared.global [%0], [%1], 16;\n" :: "r"(a), "l"(g));
}
__device__ __forceinline__ void cpcommit() { asm volatile("cp.async.commit_group;\n"); }
__device__ __forceinline__ void cpwait0()  { asm volatile("cp.async.wait_group 0;\n"); }

// x[B][T][DIN] f32 -> octet layout fp16
__global__ void xoct_kernel(const float* __restrict__ x) {
    size_t o = (size_t)blockIdx.x * blockDim.x + threadIdx.x;  // 1M octets
    int b = (int)(o & 31), j = (int)((o >> 5) & 63), t = (int)(o >> 11);
    const float* src = x + ((size_t)b * NT + t) * DIN + j * 8;
    float4 v0 = *(const float4*)src, v1 = *(const float4*)(src + 4);
    __half2 h[4];
    h[0] = __floats2half2_rn(v0.x, v0.y); h[1] = __floats2half2_rn(v0.z, v0.w);
    h[2] = __floats2half2_rn(v1.x, v1.y); h[3] = __floats2half2_rn(v1.z, v1.w);
    *(uint4*)(g_xoct + o * 8) = *(const uint4*)h;
}

// W (f32 [Ktot][4096]) -> g_WT (fp16 [4096][Ktot]), all 4 layers
__global__ void convT_kernel(const float* __restrict__ W0, const float* __restrict__ Wl) {
    __shared__ float ts[32][33];
    int bid = blockIdx.x;
    const float* src; size_t wtoff; int Ktot, tile;
    if (bid < 6144) { src = W0; wtoff = 0; Ktot = 1536; tile = bid; }
    else {
        int r = bid - 6144, l = r / 8192; tile = r % 8192;
        src = Wl + (size_t)l * 2048 * 4096;
        wtoff = (size_t)4096 * 1536 + (size_t)l * 4096 * 2048; Ktot = 2048;
    }
    int tk = tile >> 7, tn = tile & 127;
    int tx = threadIdx.x & 31, ty = threadIdx.x >> 5;
    #pragma unroll
    for (int r = 0; r < 4; ++r)
        ts[ty + r * 8][tx] = src[(size_t)(tk * 32 + ty + r * 8) * 4096 + tn * 32 + tx];
    __syncthreads();
    #pragma unroll
    for (int r = 0; r < 4; ++r)
        g_WT[wtoff + (size_t)(tn * 32 + ty + r * 8) * Ktot + tk * 32 + tx] =
            __float2half(ts[tx][ty + r * 8]);
}

// batch GEMM: Z0[m][n] = A(octet)[m][k<Kin] @ WT[n][k]^T + bias[n]
__global__ __launch_bounds__(256, 2)
void gemm_kernel(int srcsel, int njoct, size_t wtoff, int KtotS, int Kin,
                 const float* __restrict__ bias) {
    __shared__ __half sA[2][128 * 40];
    __shared__ __half sB[2][128 * 40];
    const __half* A = (srcsel == 0) ? g_xoct
                    : (srcsel == 1) ? (g_ringA + 32768) : (g_ringB + 32768);
    const __half* BT = g_WT + wtoff;
    const int tid = threadIdx.x;
    const int bm = blockIdx.x & 127, bn = blockIdx.x >> 7;
    const int wid = tid >> 5, lane = tid & 31;
    const int g = lane >> 2, tig = lane & 3;
    const int wm = wid & 3, wn = wid >> 2;

    float acc[2][8][4];
    #pragma unroll
    for (int i = 0; i < 2; ++i)
        #pragma unroll
        for (int j = 0; j < 8; ++j)
            #pragma unroll
            for (int k = 0; k < 4; ++k) acc[i][j][k] = 0.f;

    const int niter = Kin >> 5;
    auto loadAB = [&](int buf, int kt) {
        #pragma unroll
        for (int i = 0; i < 2; ++i) {
            int o = tid + i * 256, m = o >> 2, jl = o & 3;
            int tg = bm * 4 + (m >> 5), b = m & 31;
            cp16(&sA[buf][m * 40 + jl * 8],
                 A + (((size_t)tg * njoct + (size_t)(kt * 4 + jl)) * 32 + b) * 8);
            cp16(&sB[buf][m * 40 + jl * 8],
                 BT + (size_t)(bn * 128 + m) * KtotS + kt * 32 + jl * 8);
        }
    };
    loadAB(0, 0); cpcommit();
    for (int kt = 0; kt < niter; ++kt) {
        int buf = kt & 1;
        cpwait0();
        __syncthreads();
        if (kt + 1 < niter) { loadAB(buf ^ 1, kt + 1); cpcommit(); }
        #pragma unroll
        for (int ks = 0; ks < 2; ++ks) {
            const int kk = ks * 16;
            uint32_t a[2][4], b[8][2];
            #pragma unroll
            for (int mt = 0; mt < 2; ++mt) {
                const __half* ap = &sA[buf][(wm * 32 + mt * 16 + g) * 40 + kk + 2 * tig];
                a[mt][0] = *(const uint32_t*)(ap);
                a[mt][1] = *(const uint32_t*)(ap + 8 * 40);
                a[mt][2] = *(const uint32_t*)(ap + 8);
                a[mt][3] = *(const uint32_t*)(ap + 8 * 40 + 8);
            }
            #pragma unroll
            for (int nt = 0; nt < 8; ++nt) {
                const __half* bp = &sB[buf][(wn * 64 + nt * 8 + g) * 40 + kk + 2 * tig];
                b[nt][0] = *(const uint32_t*)(bp);
                b[nt][1] = *(const uint32_t*)(bp + 8);
            }
            #pragma unroll
            for (int mt = 0; mt < 2; ++mt)
                #pragma unroll
                for (int nt = 0; nt < 8; ++nt)
                    mma16816(acc[mt][nt], a[mt], b[nt]);
        }
    }
    __syncthreads();
    #pragma unroll
    for (int mt = 0; mt < 2; ++mt)
        #pragma unroll
        for (int nt = 0; nt < 8; ++nt) {
            int r0 = bm * 128 + wm * 32 + mt * 16 + g;
            int c0 = bn * 128 + wn * 64 + nt * 8 + 2 * tig;
            float b0v = bias[c0], b1v = bias[c0 + 1];
            *(float2*)(g_Z0 + (size_t)r0 * 4096 + c0) =
                make_float2(acc[mt][nt][0] + b0v, acc[mt][nt][1] + b1v);
            *(float2*)(g_Z0 + (size_t)(r0 + 8) * 4096 + c0) =
                make_float2(acc[mt][nt][2] + b0v, acc[mt][nt][3] + b1v);
        }
}

// persistent recurrent loop for one layer: z(t)=Z0[t]+h(t-1)@Wh; gates; h->slot t+1
__global__ __launch_bounds__(NTHREADS, 1)
void loop_kernel(int ringsel, const float* __restrict__ h0l, const float* __restrict__ c0l,
                 size_t wtoff, int KtotS, int Kin, int lastflag, unsigned barbase) {
    __shared__ float sred[8 * 1024 + 1024];
    float* partials = sred;
    float* zbuf = sred + 8 * 1024;
    __half* ring = ringsel ? g_ringB : g_ringA;
    const __half* WT_l = g_WT + wtoff;

    const int tid = threadIdx.x, cta = blockIdx.x;
    const int wid = tid >> 5, lane = tid & 31;
    const int g = lane >> 2, tig = lane & 3;
    const int rb = tid >> 3, rd = tid & 7;

    // recurrent weights -> registers for whole launch (validated fragment map)
    uint32_t wreg[8][4][2];
    #pragma unroll
    for (int it = 0; it < 8; ++it)
        #pragma unroll
        for (int nt = 0; nt < 4; ++nt) {
            const __half* p = WT_l + (size_t)(nt * HID + cta * 8 + g) * KtotS
                            + Kin + wid * 128 + it * 16 + 2 * tig;
            wreg[it][nt][0] = *(const uint32_t*)(p);
            wreg[it][nt][1] = *(const uint32_t*)(p + 8);
        }

    float c_state = c0l[rb * HID + cta * 8 + rd];

    // prologue: slot 0 = h0
    ring[(size_t)cta * 256 + rb * 8 + rd] = __float2half(h0l[rb * HID + cta * 8 + rd]);
    bar_arrive();
    unsigned waitcnt = barbase + NCTA;

    const size_t myoff = (size_t)(wid * 16) * 256 + g * 8 + 2 * tig;

    for (int t = 0; t < NT; ++t) {
        float z0r[4];
        {
            const float* zp = g_Z0 + ((size_t)(t * NB + rb)) * 4096 + cta * 8 + rd;
            #pragma unroll
            for (int gg = 0; gg < 4; ++gg) z0r[gg] = __ldcg(zp + gg * HID);
        }

        bar_wait(waitcnt);

        const __half* hp = ring + (size_t)t * 32768 + myoff;
        uint32_t areg[8][8];
        #pragma unroll
        for (int it = 0; it < 8; ++it) {
            const __half* p = hp + it * 512;
            areg[it][0] = __ldcg((const uint32_t*)(p));
            areg[it][1] = __ldcg((const uint32_t*)(p + 64));
            areg[it][2] = __ldcg((const uint32_t*)(p + 256));
            areg[it][3] = __ldcg((const uint32_t*)(p + 320));
            areg[it][4] = __ldcg((const uint32_t*)(p + 128));
            areg[it][5] = __ldcg((const uint32_t*)(p + 192));
            areg[it][6] = __ldcg((const uint32_t*)(p + 384));
            areg[it][7] = __ldcg((const uint32_t*)(p + 448));
        }

        float acc[2][4][4];
        #pragma unroll
        for (int i = 0; i < 2; ++i)
            #pragma unroll
            for (int j = 0; j < 4; ++j)
                #pragma unroll
                for (int k = 0; k < 4; ++k) acc[i][j][k] = 0.f;
        #pragma unroll
        for (int it = 0; it < 8; ++it)
            #pragma unroll
            for (int nt = 0; nt < 4; ++nt) {
                mma16816(acc[0][nt], &areg[it][0], wreg[it][nt]);
                mma16816(acc[1][nt], &areg[it][4], wreg[it][nt]);
            }

        {
            float* P = partials + wid * 1024;
            #pragma unroll
            for (int mt = 0; mt < 2; ++mt)
                #pragma unroll
                for (int nt = 0; nt < 4; ++nt) {
                    int r = mt * 16 + g, cc = nt * 8 + 2 * tig;
                    *(float2*)(P + r * 32 + cc) = make_float2(acc[mt][nt][0], acc[mt][nt][1]);
                    *(float2*)(P + (r + 8) * 32 + cc) = make_float2(acc[mt][nt][2], acc[mt][nt][3]);
                }
        }
        __syncthreads();
        {
            int e0 = tid * 4;
            float4 s = make_float4(0.f, 0.f, 0.f, 0.f);
            #pragma unroll
            for (int w = 0; w < 8; ++w) {
                float4 v = *(const float4*)(partials + w * 1024 + e0);
                s.x += v.x; s.y += v.y; s.z += v.z; s.w += v.w;
            }
            *(float4*)(zbuf + e0) = s;
        }
        __syncthreads();
        {
            float zi = zbuf[rb * 32 +  0 + rd] + z0r[0];
            float zf = zbuf[rb * 32 +  8 + rd] + z0r[1];
            float zg = zbuf[rb * 32 + 16 + rd] + z0r[2];
            float zo = zbuf[rb * 32 + 24 + rd] + z0r[3];
            float si = 1.f / (1.f + __expf(-zi));
            float sf = 1.f / (1.f + __expf(-zf));
            float so = 1.f / (1.f + __expf(-zo));
            float tg = tanhf(zg);
            c_state = sf * c_state + si * tg;
            float h = so * tanhf(c_state);
            ring[(size_t)(t + 1) * 32768 + (size_t)cta * 256 + rb * 8 + rd] = __float2half(h);
            if (lastflag && t == NT - 1) g_hlast[rb * HID + cta * 8 + rd] = h;
        }
        bar_arrive();
        waitcnt += NCTA;
    }
}

// dense head with 4-way ILP accumulators
__global__ void head_kernel(const float* __restrict__ Wout,
                            const float* __restrict__ bout,
                            float* __restrict__ out) {
    __shared__ float hsh[HID];
    int b = blockIdx.x;
    for (int i = threadIdx.x; i < HID; i += blockDim.x) hsh[i] = g_hlast[b * HID + i];
    __syncthreads();
    int o = threadIdx.x;
    float s0 = bout[o], s1 = 0.f, s2 = 0.f, s3 = 0.f;
    #pragma unroll 4
    for (int k = 0; k < HID; k += 4) {
        s0 += hsh[k]     * Wout[(size_t)k * NOUT + o];
        s1 += hsh[k + 1] * Wout[(size_t)(k + 1) * NOUT + o];
        s2 += hsh[k + 2] * Wout[(size_t)(k + 2) * NOUT + o];
        s3 += hsh[k + 3] * Wout[(size_t)(k + 3) * NOUT + o];
    }
    out[(size_t)b * NOUT + o] = (s0 + s1) + (s2 + s3);
}

extern "C" void kernel_launch(void* const* d_in, const int* in_sizes, int n_in,
                              void* d_out, int out_size) {
    const float* x    = (const float*)d_in[0];
    const float* h0   = (const float*)d_in[1];
    const float* c0   = (const float*)d_in[2];
    const float* W0   = (const float*)d_in[3];
    const float* b0   = (const float*)d_in[4];
    const float* Wl   = (const float*)d_in[5];
    const float* bl   = (const float*)d_in[6];
    const float* Wout = (const float*)d_in[7];
    const float* bout = (const float*)d_in[8];
    float* out = (float*)d_out;

    const size_t HB = (size_t)NB * HID;
    const size_t wt0 = 0;
    const size_t wt1 = (size_t)4096 * 1536;
    const size_t wt2 = wt1 + (size_t)4096 * 2048;
    const size_t wt3 = wt2 + (size_t)4096 * 2048;
    const unsigned per = (unsigned)((NT + 1) * NCTA);

    reset_kernel<<<1, 32>>>();
    xoct_kernel<<<4096, 256>>>(x);
    convT_kernel<<<30720, 256>>>(W0, Wl);

    // layer 0
    gemm_kernel<<<4096, 256>>>(0, 64, wt0, 1536, 512, b0);
    loop_kernel<<<NCTA, NTHREADS>>>(0, h0, c0, wt0, 1536, 512, 0, 0 * per);
    // layer 1 (reads ringA)
    gemm_kernel<<<4096, 256>>>(1, 128, wt1, 2048, 1024, bl);
    loop_kernel<<<NCTA, NTHREADS>>>(1, h0 + HB, c0 + HB, wt1, 2048, 1024, 0, 1 * per);
    // layer 2 (reads ringB)
    gemm_kernel<<<4096, 256>>>(2, 128, wt2, 2048, 1024, bl + 4096);
    loop_kernel<<<NCTA, NTHREADS>>>(0, h0 + 2 * HB, c0 + 2 * HB, wt2, 2048, 1024, 0, 2 * per);
    // layer 3 (reads ringA)
    gemm_kernel<<<4096, 256>>>(1, 128, wt3, 2048, 1024, bl + 2 * 4096);
    loop_kernel<<<NCTA, NTHREADS>>>(1, h0 + 3 * HB, c0 + 3 * HB, wt3, 2048, 1024, 1, 3 * per);

    head_kernel<<<NB, 1024>>>(Wout, bout, out);
}